// round 10
// baseline (speedup 1.0000x reference)
#include <cuda_runtime.h>
#include <cuda_fp16.h>
#include <cstdint>

#define D_   1024
#define H_   16
#define HD_  64
#define B_   2
#define S_   2048
#define M_   (B_ * S_)          // 4096

// ---------------- scratch (device globals) ---------------------------------
__device__ unsigned g_q16[(size_t)M_ * D_ / 2];     // fp16 natural inputs
__device__ unsigned g_k16[(size_t)M_ * D_ / 2];
__device__ unsigned g_v16[(size_t)M_ * D_ / 2];
__device__ unsigned g_w16[4][(size_t)D_ * D_ / 2];  // Wq,Wk,Wv,Wo fp16
__device__ unsigned g_Qh[(size_t)M_ * D_ / 2];      // [B,H,S,32w] natural, *SC
__device__ unsigned g_Kh[(size_t)M_ * D_ / 2];      // [B,H,S,32w] natural
__device__ unsigned g_Vh[(size_t)M_ * D_ / 2];      // [B,H,64,S] natural (transposed)
__device__ unsigned g_Ch[(size_t)M_ * D_ / 2];      // ctx [M,512w] natural

#define SC_Q 0.18033688011112042f   /* 0.125 * log2(e) */

// ---------------------------------------------------------------------------
// helpers
// ---------------------------------------------------------------------------
__device__ __forceinline__ unsigned pack2(float lo, float hi) {
    unsigned r;
    asm("cvt.rn.f16x2.f32 %0, %1, %2;" : "=r"(r) : "f"(hi), "f"(lo));
    return r;
}
__device__ __forceinline__ float ex2(float x) {
    float y; asm("ex2.approx.ftz.f32 %0, %1;" : "=f"(y) : "f"(x)); return y;
}
__device__ __forceinline__ void mma_f16(float c[4], const unsigned a[4], unsigned b0, unsigned b1) {
    asm volatile(
        "mma.sync.aligned.m16n8k16.row.col.f32.f16.f16.f32 "
        "{%0,%1,%2,%3}, {%4,%5,%6,%7}, {%8,%9}, {%0,%1,%2,%3};\n"
        : "+f"(c[0]), "+f"(c[1]), "+f"(c[2]), "+f"(c[3])
        : "r"(a[0]), "r"(a[1]), "r"(a[2]), "r"(a[3]), "r"(b0), "r"(b1));
}
__device__ __forceinline__ void ldsm4(unsigned& r0, unsigned& r1, unsigned& r2, unsigned& r3,
                                      unsigned addr) {
    asm volatile("ldmatrix.sync.aligned.m8n8.x4.shared.b16 {%0,%1,%2,%3}, [%4];"
                 : "=r"(r0), "=r"(r1), "=r"(r2), "=r"(r3) : "r"(addr));
}
#define CP16(dst, src) \
    asm volatile("cp.async.cg.shared.global [%0], [%1], 16;" :: "r"(dst), "l"(src) : "memory")
#define CP_COMMIT() asm volatile("cp.async.commit_group;" ::: "memory")
#define CP_WAIT1()  asm volatile("cp.async.wait_group 1;" ::: "memory")
#define CP_WAIT0()  asm volatile("cp.async.wait_group 0;" ::: "memory")

// ---------------------------------------------------------------------------
// convert: fp32 -> fp16 natural (q,k,v + 4 weights)
// ---------------------------------------------------------------------------
__global__ __launch_bounds__(256) void convert_kernel(
    const float* __restrict__ q, const float* __restrict__ k, const float* __restrict__ v,
    const float* __restrict__ wq, const float* __restrict__ wk,
    const float* __restrict__ wv, const float* __restrict__ wo)
{
    const int z = blockIdx.z;
    const float* src;
    unsigned* dst;
    size_t n;
    switch (z) {
        case 0: src = q;  dst = g_q16;    n = (size_t)M_ * D_; break;
        case 1: src = k;  dst = g_k16;    n = (size_t)M_ * D_; break;
        case 2: src = v;  dst = g_v16;    n = (size_t)M_ * D_; break;
        case 3: src = wq; dst = g_w16[0]; n = (size_t)D_ * D_; break;
        case 4: src = wk; dst = g_w16[1]; n = (size_t)D_ * D_; break;
        case 5: src = wv; dst = g_w16[2]; n = (size_t)D_ * D_; break;
        default: src = wo; dst = g_w16[3]; n = (size_t)D_ * D_; break;
    }
    const size_t i8 = ((size_t)blockIdx.x * blockDim.x + threadIdx.x) * 8;
    if (i8 >= n) return;
    float4 f0 = *(const float4*)(src + i8);
    float4 f1 = *(const float4*)(src + i8 + 4);
    uint4 o = make_uint4(pack2(f0.x, f0.y), pack2(f0.z, f0.w),
                         pack2(f1.x, f1.y), pack2(f1.z, f1.w));
    *(uint4*)(dst + i8 / 2) = o;
}

// ---------------------------------------------------------------------------
// fp16 GEMM: C[m,e] = A[m,:] . W[e,:] + bias[e]
// CTA 128x128, 256 threads (8 warps 4x2, warp tile 32x64), BK=64 halves,
// 3-stage cp.async, SW128 smem, ldmatrix fragments.  2 CTAs/SM = 16 warps/SM.
// modes: 0 float out [M,D]; 1 Q natural *SC; 2 K natural; 3 V transposed nat.
// ---------------------------------------------------------------------------
#define GSTG   3
#define TILEB  16384
#define GM_SMEM (GSTG * 2 * TILEB)   // 98304

__device__ __forceinline__ void gemm16_body(
    const unsigned* __restrict__ Aw,
    const unsigned* __restrict__ Ww,
    const float* __restrict__ bias,
    void* __restrict__ outp,
    int mode)
{
    extern __shared__ char smc[];
    const unsigned smA = (unsigned)__cvta_generic_to_shared(smc);
    const unsigned smB = smA + GSTG * TILEB;

    const int t    = threadIdx.x;
    const int lane = t & 31;
    const int w    = t >> 5;
    const int gp   = lane >> 2;
    const int tg   = lane & 3;
    const int wm0  = (w >> 1) << 5;       // 4 m-slots of 32
    const int wn0  = (w & 1) << 6;        // 2 n-slots of 64

    const int m0 = blockIdx.y << 7;
    const int n0 = blockIdx.x << 7;

    const unsigned* Ab = Aw + (size_t)m0 * 512;
    const unsigned* Bb = Ww + (size_t)n0 * 512;

    const int lr = t >> 3;     // 0..31
    const int lc = t & 7;

    const int la15 = lane & 15;
    const int ahi  = (lane >> 4) << 4;
    const int bsel = ((lane >> 3) & 1) << 4;
    const int brow0 = wn0 + ((lane >> 4) << 3) + (lane & 7);

    int arow[2], akey[2];
#pragma unroll
    for (int mi = 0; mi < 2; mi++) {
        const int r = wm0 + 16 * mi + la15;
        arow[mi] = 128 * r;
        akey[mi] = (r & 7) << 4;
    }

    float acc[2][8][4];
#pragma unroll
    for (int mi = 0; mi < 2; mi++)
#pragma unroll
        for (int nj = 0; nj < 8; nj++)
#pragma unroll
            for (int q = 0; q < 4; q++) acc[mi][nj][q] = 0.0f;

#define GISSUE(st, kc) do {                                                    \
    const unsigned da = smA + (st) * TILEB;                                    \
    const unsigned db = smB + (st) * TILEB;                                    \
    _Pragma("unroll")                                                          \
    for (int i = 0; i < 4; i++) {                                              \
        const int row = lr + 32 * i;                                           \
        const unsigned off = 128u * row + ((16u * lc) ^ ((row & 7) << 4));     \
        CP16(da + off, Ab + (size_t)row * 512 + (kc) * 32 + 4 * lc);           \
        CP16(db + off, Bb + (size_t)row * 512 + (kc) * 32 + 4 * lc);           \
    }                                                                          \
    CP_COMMIT();                                                               \
} while (0)

    GISSUE(0, 0);
    GISSUE(1, 1);

    for (int kc = 0; kc < 16; kc++) {
        if (kc == 15) { CP_WAIT0(); } else { CP_WAIT1(); }
        __syncthreads();
        if (kc + 2 < 16) {
            const int st = (kc + 2) % 3;
            GISSUE(st, kc + 2);
        }

        const unsigned ab = smA + (kc % 3) * TILEB;
        const unsigned bb = smB + (kc % 3) * TILEB;

#pragma unroll
        for (int s = 0; s < 4; s++) {
            unsigned a[2][4];
#pragma unroll
            for (int mi = 0; mi < 2; mi++) {
                const unsigned addr = ab + arow[mi] + ((32 * s + ahi) ^ akey[mi]);
                ldsm4(a[mi][0], a[mi][1], a[mi][2], a[mi][3], addr);
            }
#pragma unroll
            for (int nj2 = 0; nj2 < 4; nj2++) {
                const int row = brow0 + 16 * nj2;
                const unsigned addr = bb + 128u * row + ((32 * s + bsel) ^ ((row & 7) << 4));
                unsigned b0, b1, b2, b3;
                ldsm4(b0, b1, b2, b3, addr);
#pragma unroll
                for (int mi = 0; mi < 2; mi++) {
                    mma_f16(acc[mi][2 * nj2],     a[mi], b0, b1);
                    mma_f16(acc[mi][2 * nj2 + 1], a[mi], b2, b3);
                }
            }
        }
    }
#undef GISSUE

    // ---- epilogue
#pragma unroll
    for (int mi = 0; mi < 2; mi++) {
#pragma unroll
        for (int h = 0; h < 2; h++) {
            const int m  = m0 + wm0 + 16 * mi + gp + 8 * h;
            const int b_ = m >> 11;
            const int s  = m & (S_ - 1);
#pragma unroll
            for (int nj = 0; nj < 8; nj++) {
                const int e  = n0 + wn0 + 8 * nj + 2 * tg;
                const float vx = acc[mi][nj][2 * h]     + bias[e];
                const float vy = acc[mi][nj][2 * h + 1] + bias[e + 1];
                if (mode == 0) {
                    *(float2*)((float*)outp + (size_t)m * D_ + e) = make_float2(vx, vy);
                } else if (mode == 1 || mode == 2) {
                    const int hh = e >> 6, hd = e & 63;
                    const float sc = (mode == 1) ? SC_Q : 1.0f;
                    ((unsigned*)outp)[(((size_t)(b_ * H_ + hh) * S_ + s) << 5) + (hd >> 1)] =
                        pack2(vx * sc, vy * sc);
                } else {
                    // V: natural transposed [b,h,hd][s]
                    const int hh = e >> 6, hd = e & 63;
                    __half* vo = (__half*)outp + (((size_t)(b_ * H_ + hh) * HD_ + hd)) * S_ + s;
                    vo[0]  = __float2half_rn(vx);
                    vo[S_] = __float2half_rn(vy);
                }
            }
        }
    }
}

__global__ __launch_bounds__(256, 2) void qkv_gemm_kernel(
    const float* __restrict__ bq, const float* __restrict__ bk, const float* __restrict__ bv)
{
    const int z = blockIdx.z;
    const unsigned* A = (z == 0) ? g_q16 : (z == 1) ? g_k16 : g_v16;
    const float* b    = (z == 0) ? bq : (z == 1) ? bk : bv;
    void* o           = (z == 0) ? (void*)g_Qh : (z == 1) ? (void*)g_Kh : (void*)g_Vh;
    gemm16_body(A, g_w16[z], b, o, z + 1);
}

__global__ __launch_bounds__(256, 2) void out_gemm_kernel(
    const float* __restrict__ bo, float* __restrict__ out)
{
    gemm16_body(g_Ch, g_w16[3], bo, (void*)out, 0);
}

// ---------------------------------------------------------------------------
// Flash attention fp16. 256 threads (8 warps), Q-tile 128 (16 rows/warp),
// K-tile 64, 3-stage cp.async, ldmatrix K AND V frags, deferred l-sum,
// conditional rescale.  K and V stages both SW128 64x128B (8192 B).
// ---------------------------------------------------------------------------
#define FL_KSTG 8192
#define FL_VSTG 8192
#define FL_SMEM (3 * (FL_KSTG + FL_VSTG))   // 49152

__global__ __launch_bounds__(256, 2) void flash_fp16_kernel()
{
    extern __shared__ char fsm[];
    const unsigned smK = (unsigned)__cvta_generic_to_shared(fsm);
    const unsigned smV = smK + 3 * FL_KSTG;

    const int t    = threadIdx.x;
    const int lane = t & 31;
    const int w    = t >> 5;
    const int gp   = lane >> 2;
    const int tg   = lane & 3;
    const int qr0  = w << 4;

    const int bh = blockIdx.y;
    const int q0 = blockIdx.x << 7;

    const unsigned* Qw = g_Qh + (size_t)bh * S_ * 32;
    const unsigned* Kw = g_Kh + (size_t)bh * S_ * 32;
    const unsigned* Vw = g_Vh + (size_t)bh * HD_ * (S_ / 2);

    // loader: rows kr0, kr0+32 for both K (keys) and V (d)
    const int kr0 = t >> 3;
    const int kj  = t & 7;
    const unsigned off0 = 128u * kr0 + ((16u * kj) ^ ((kr0 & 7) << 4));
    const unsigned off1 = 128u * (kr0 + 32) + ((16u * kj) ^ (((kr0 + 32) & 7) << 4));

#define FISSUE(st, it2) do {                                                     \
    const int kn = (it2) << 6;                                                   \
    CP16(smK + (st) * FL_KSTG + off0, Kw + (size_t)(kn + kr0) * 32 + 4 * kj);    \
    CP16(smK + (st) * FL_KSTG + off1, Kw + (size_t)(kn + kr0 + 32) * 32 + 4 * kj); \
    CP16(smV + (st) * FL_VSTG + off0,                                            \
         Vw + (size_t)kr0 * (S_ / 2) + (it2) * 32 + 4 * kj);                     \
    CP16(smV + (st) * FL_VSTG + off1,                                            \
         Vw + (size_t)(kr0 + 32) * (S_ / 2) + (it2) * 32 + 4 * kj);              \
    CP_COMMIT();                                                                 \
} while (0)

    // ---- Q fragments (natural layout, pre-scaled by SC_Q)
    unsigned qa[4][4];
#pragma unroll
    for (int s = 0; s < 4; s++) {
        const unsigned* r0 = Qw + (size_t)(q0 + qr0 + gp) * 32;
        const unsigned* r1 = Qw + (size_t)(q0 + qr0 + 8 + gp) * 32;
        qa[s][0] = r0[8 * s + tg];
        qa[s][1] = r1[8 * s + tg];
        qa[s][2] = r0[8 * s + tg + 4];
        qa[s][3] = r1[8 * s + tg + 4];
    }

    FISSUE(0, 0);
    FISSUE(1, 1);

    const int kbrow0 = ((lane >> 4) << 3) + (lane & 7);
    const int kbsel  = ((lane >> 3) & 1) << 4;

    float m_i[2] = {-1e30f, -1e30f};
    float l_i[2] = {0.0f, 0.0f};
    float o[8][4];
#pragma unroll
    for (int dj = 0; dj < 8; dj++)
#pragma unroll
        for (int q = 0; q < 4; q++) o[dj][q] = 0.0f;

    for (int it = 0; it < 32; it++) {
        if (it == 31) { CP_WAIT0(); } else { CP_WAIT1(); }
        __syncthreads();
        if (it + 2 < 32) FISSUE((it + 2) % 3, it + 2);

        const unsigned kb = smK + (it % 3) * FL_KSTG;
        const unsigned vb = smV + (it % 3) * FL_VSTG;

        // ---- S = Q K^T  (64 keys)
        float s[8][4];
#pragma unroll
        for (int nj = 0; nj < 8; nj++)
#pragma unroll
            for (int q = 0; q < 4; q++) s[nj][q] = 0.0f;

#pragma unroll
        for (int ks = 0; ks < 4; ks++) {
#pragma unroll
            for (int nj2 = 0; nj2 < 4; nj2++) {
                const int row = 16 * nj2 + kbrow0;
                const unsigned addr = kb + 128u * row + ((32 * ks + kbsel) ^ ((row & 7) << 4));
                unsigned b0, b1, b2, b3;
                ldsm4(b0, b1, b2, b3, addr);
                mma_f16(s[2 * nj2],     qa[ks], b0, b1);
                mma_f16(s[2 * nj2 + 1], qa[ks], b2, b3);
            }
        }

        // ---- online softmax (exp2 domain; deferred l-sum; cond. rescale)
#pragma unroll
        for (int h = 0; h < 2; h++) {
            float mx = fmaxf(s[0][2 * h], s[0][2 * h + 1]);
#pragma unroll
            for (int nj = 1; nj < 8; nj++)
                mx = fmaxf(mx, fmaxf(s[nj][2 * h], s[nj][2 * h + 1]));
            mx = fmaxf(mx, __shfl_xor_sync(0xffffffffu, mx, 1));
            mx = fmaxf(mx, __shfl_xor_sync(0xffffffffu, mx, 2));
            if (mx > m_i[h]) {
                const float corr = ex2(m_i[h] - mx);
                m_i[h] = mx;
                l_i[h] *= corr;
#pragma unroll
                for (int dj = 0; dj < 8; dj++) {
                    o[dj][2 * h]     *= corr;
                    o[dj][2 * h + 1] *= corr;
                }
            }
            float rs = 0.0f;
#pragma unroll
            for (int nj = 0; nj < 8; nj++) {
                s[nj][2 * h]     = ex2(s[nj][2 * h] - m_i[h]);
                s[nj][2 * h + 1] = ex2(s[nj][2 * h + 1] - m_i[h]);
                rs += s[nj][2 * h] + s[nj][2 * h + 1];
            }
            l_i[h] += rs;
        }

        // ---- P fragments
        unsigned pa[4][4];
#pragma unroll
        for (int cp = 0; cp < 4; cp++) {
            pa[cp][0] = pack2(s[2 * cp][0],     s[2 * cp][1]);
            pa[cp][1] = pack2(s[2 * cp][2],     s[2 * cp][3]);
            pa[cp][2] = pack2(s[2 * cp + 1][0], s[2 * cp + 1][1]);
            pa[cp][3] = pack2(s[2 * cp + 1][2], s[2 * cp + 1][3]);
        }

        // ---- O += P @ V (ldmatrix V frags, natural layout)
#pragma unroll
        for (int cp = 0; cp < 4; cp++) {
#pragma unroll
            for (int dj2 = 0; dj2 < 4; dj2++) {
                const int row = 16 * dj2 + kbrow0;
                const unsigned addr = vb + 128u * row + ((32 * cp + kbsel) ^ ((row & 7) << 4));
                unsigned b0, b1, b2, b3;
                ldsm4(b0, b1, b2, b3, addr);
                mma_f16(o[2 * dj2],     pa[cp], b0, b1);
                mma_f16(o[2 * dj2 + 1], pa[cp], b2, b3);
            }
        }
    }
#undef FISSUE

    // ---- finalize l, write ctx natural fp16
    const int b_ = bh >> 4;
    const int hh = bh & 15;
#pragma unroll
    for (int h = 0; h < 2; h++) {
        float l = l_i[h];
        l += __shfl_xor_sync(0xffffffffu, l, 1);
        l += __shfl_xor_sync(0xffffffffu, l, 2);
        const float inv = 1.0f / l;
        const int srow = q0 + qr0 + gp + 8 * h;
        unsigned* co = g_Ch + ((size_t)(b_ * S_ + srow) << 9) + (hh << 5);
#pragma unroll
        for (int dj = 0; dj < 8; dj++)
            co[4 * dj + tg] = pack2(o[dj][2 * h] * inv, o[dj][2 * h + 1] * inv);
    }
}

// ---------------------------------------------------------------------------
extern "C" void kernel_launch(void* const* d_in, const int* in_sizes, int n_in,
                              void* d_out, int out_size)
{
    const float* query = (const float*)d_in[0];
    const float* key   = (const float*)d_in[1];
    const float* value = (const float*)d_in[2];
    const float* Wq    = (const float*)d_in[3];
    const float* bq    = (const float*)d_in[4];
    const float* Wk    = (const float*)d_in[5];
    const float* bk    = (const float*)d_in[6];
    const float* Wv    = (const float*)d_in[7];
    const float* bv    = (const float*)d_in[8];
    const float* Wo    = (const float*)d_in[9];
    const float* bo    = (const float*)d_in[10];

    static int smem_set = 0;
    if (!smem_set) {
        cudaFuncSetAttribute(qkv_gemm_kernel,
                             cudaFuncAttributeMaxDynamicSharedMemorySize, GM_SMEM);
        cudaFuncSetAttribute(out_gemm_kernel,
                             cudaFuncAttributeMaxDynamicSharedMemorySize, GM_SMEM);
        cudaFuncSetAttribute(flash_fp16_kernel,
                             cudaFuncAttributeMaxDynamicSharedMemorySize, FL_SMEM);
        smem_set = 1;
    }

    convert_kernel<<<dim3(2048, 1, 7), 256>>>(query, key, value, Wq, Wk, Wv, Wo);

    qkv_gemm_kernel<<<dim3(D_ / 128, M_ / 128, 3), 256, GM_SMEM>>>(bq, bk, bv);

    flash_fp16_kernel<<<dim3(S_ / 128, B_ * H_), 256, FL_SMEM>>>();

    out_gemm_kernel<<<dim3(D_ / 128, M_ / 128), 256, GM_SMEM>>>(bo, (float*)d_out);
}

// round 11
// speedup vs baseline: 1.0178x; 1.0178x over previous
#include <cuda_runtime.h>
#include <cuda_fp16.h>
#include <cstdint>

#define D_   1024
#define H_   16
#define HD_  64
#define B_   2
#define S_   2048
#define M_   (B_ * S_)          // 4096

// ---------------- scratch (device globals) ---------------------------------
__device__ unsigned g_q16[(size_t)M_ * D_ / 2];     // fp16 natural inputs
__device__ unsigned g_k16[(size_t)M_ * D_ / 2];
__device__ unsigned g_v16[(size_t)M_ * D_ / 2];
__device__ unsigned g_w16[4][(size_t)D_ * D_ / 2];  // Wq,Wk,Wv,Wo fp16
__device__ unsigned g_Qh[(size_t)M_ * D_ / 2];      // [B,H,S,32w] natural, *SC
__device__ unsigned g_Kh[(size_t)M_ * D_ / 2];      // [B,H,S,32w] natural
__device__ unsigned g_Vh[(size_t)M_ * D_ / 2];      // [B,H,64,S] natural (transposed)
__device__ unsigned g_Ch[(size_t)M_ * D_ / 2];      // ctx [M,512w] natural

#define SC_Q 0.18033688011112042f   /* 0.125 * log2(e) */
#define ONES2 0x3C003C00u           /* (1.0h, 1.0h) */

// ---------------------------------------------------------------------------
// helpers
// ---------------------------------------------------------------------------
__device__ __forceinline__ unsigned pack2(float lo, float hi) {
    unsigned r;
    asm("cvt.rn.f16x2.f32 %0, %1, %2;" : "=r"(r) : "f"(hi), "f"(lo));
    return r;
}
__device__ __forceinline__ float ex2(float x) {
    float y; asm("ex2.approx.ftz.f32 %0, %1;" : "=f"(y) : "f"(x)); return y;
}
__device__ __forceinline__ unsigned ex2h2(unsigned x) {
    unsigned y; asm("ex2.approx.f16x2 %0, %1;" : "=r"(y) : "r"(x)); return y;
}
__device__ __forceinline__ void mma_f16(float c[4], const unsigned a[4], unsigned b0, unsigned b1) {
    asm volatile(
        "mma.sync.aligned.m16n8k16.row.col.f32.f16.f16.f32 "
        "{%0,%1,%2,%3}, {%4,%5,%6,%7}, {%8,%9}, {%0,%1,%2,%3};\n"
        : "+f"(c[0]), "+f"(c[1]), "+f"(c[2]), "+f"(c[3])
        : "r"(a[0]), "r"(a[1]), "r"(a[2]), "r"(a[3]), "r"(b0), "r"(b1));
}
__device__ __forceinline__ void ldsm4(unsigned& r0, unsigned& r1, unsigned& r2, unsigned& r3,
                                      unsigned addr) {
    asm volatile("ldmatrix.sync.aligned.m8n8.x4.shared.b16 {%0,%1,%2,%3}, [%4];"
                 : "=r"(r0), "=r"(r1), "=r"(r2), "=r"(r3) : "r"(addr));
}
#define CP16(dst, src) \
    asm volatile("cp.async.cg.shared.global [%0], [%1], 16;" :: "r"(dst), "l"(src) : "memory")
#define CP_COMMIT() asm volatile("cp.async.commit_group;" ::: "memory")
#define CP_WAIT1()  asm volatile("cp.async.wait_group 1;" ::: "memory")
#define CP_WAIT0()  asm volatile("cp.async.wait_group 0;" ::: "memory")

// ---------------------------------------------------------------------------
// convert: fp32 -> fp16 natural (q,k,v + 4 weights)
// ---------------------------------------------------------------------------
__global__ __launch_bounds__(256) void convert_kernel(
    const float* __restrict__ q, const float* __restrict__ k, const float* __restrict__ v,
    const float* __restrict__ wq, const float* __restrict__ wk,
    const float* __restrict__ wv, const float* __restrict__ wo)
{
    const int z = blockIdx.z;
    const float* src;
    unsigned* dst;
    size_t n;
    switch (z) {
        case 0: src = q;  dst = g_q16;    n = (size_t)M_ * D_; break;
        case 1: src = k;  dst = g_k16;    n = (size_t)M_ * D_; break;
        case 2: src = v;  dst = g_v16;    n = (size_t)M_ * D_; break;
        case 3: src = wq; dst = g_w16[0]; n = (size_t)D_ * D_; break;
        case 4: src = wk; dst = g_w16[1]; n = (size_t)D_ * D_; break;
        case 5: src = wv; dst = g_w16[2]; n = (size_t)D_ * D_; break;
        default: src = wo; dst = g_w16[3]; n = (size_t)D_ * D_; break;
    }
    const size_t i8 = ((size_t)blockIdx.x * blockDim.x + threadIdx.x) * 8;
    if (i8 >= n) return;
    float4 f0 = *(const float4*)(src + i8);
    float4 f1 = *(const float4*)(src + i8 + 4);
    uint4 o = make_uint4(pack2(f0.x, f0.y), pack2(f0.z, f0.w),
                         pack2(f1.x, f1.y), pack2(f1.z, f1.w));
    *(uint4*)(dst + i8 / 2) = o;
}

// ---------------------------------------------------------------------------
// fp16 GEMM (round-9 proven config): CTA 128x128, 128 threads (4 warps 2x2,
// warp tile 64x64), BK=64 halves, 3-stage cp.async, SW128 smem, ldmatrix.
// modes: 0 float out [M,D]; 1 Q natural *SC; 2 K natural; 3 V transposed nat.
// ---------------------------------------------------------------------------
#define GSTG   3
#define TILEB  16384
#define GM_SMEM (GSTG * 2 * TILEB)   // 98304

__device__ __forceinline__ void gemm16_body(
    const unsigned* __restrict__ Aw,
    const unsigned* __restrict__ Ww,
    const float* __restrict__ bias,
    void* __restrict__ outp,
    int mode)
{
    extern __shared__ char smc[];
    const unsigned smA = (unsigned)__cvta_generic_to_shared(smc);
    const unsigned smB = smA + GSTG * TILEB;

    const int t    = threadIdx.x;
    const int lane = t & 31;
    const int w    = t >> 5;
    const int gp   = lane >> 2;
    const int tg   = lane & 3;
    const int wm0  = (w >> 1) << 6;
    const int wn0  = (w & 1) << 6;

    const int m0 = blockIdx.y << 7;
    const int n0 = blockIdx.x << 7;

    const unsigned* Ab = Aw + (size_t)m0 * 512;
    const unsigned* Bb = Ww + (size_t)n0 * 512;

    const int lr = t >> 3;
    const int lc = t & 7;

    const int la15 = lane & 15;
    const int ahi  = (lane >> 4) << 4;
    const int bsel = ((lane >> 3) & 1) << 4;
    const int brow0 = wn0 + ((lane >> 4) << 3) + (lane & 7);

    int arow[4], akey[4];
#pragma unroll
    for (int mi = 0; mi < 4; mi++) {
        const int r = wm0 + 16 * mi + la15;
        arow[mi] = 128 * r;
        akey[mi] = (r & 7) << 4;
    }

    float acc[4][8][4];
#pragma unroll
    for (int mi = 0; mi < 4; mi++)
#pragma unroll
        for (int nj = 0; nj < 8; nj++)
#pragma unroll
            for (int q = 0; q < 4; q++) acc[mi][nj][q] = 0.0f;

#define GISSUE(st, kc) do {                                                    \
    const unsigned da = smA + (st) * TILEB;                                    \
    const unsigned db = smB + (st) * TILEB;                                    \
    _Pragma("unroll")                                                          \
    for (int i = 0; i < 8; i++) {                                              \
        const int row = lr + 16 * i;                                           \
        const unsigned off = 128u * row + ((16u * lc) ^ ((row & 7) << 4));     \
        CP16(da + off, Ab + (size_t)row * 512 + (kc) * 32 + 4 * lc);           \
        CP16(db + off, Bb + (size_t)row * 512 + (kc) * 32 + 4 * lc);           \
    }                                                                          \
    CP_COMMIT();                                                               \
} while (0)

    GISSUE(0, 0);
    GISSUE(1, 1);

    for (int kc = 0; kc < 16; kc++) {
        if (kc == 15) { CP_WAIT0(); } else { CP_WAIT1(); }
        __syncthreads();
        if (kc + 2 < 16) {
            const int st = (kc + 2) % 3;
            GISSUE(st, kc + 2);
        }

        const unsigned ab = smA + (kc % 3) * TILEB;
        const unsigned bb = smB + (kc % 3) * TILEB;

#pragma unroll
        for (int s = 0; s < 4; s++) {
            unsigned a[4][4];
#pragma unroll
            for (int mi = 0; mi < 4; mi++) {
                const unsigned addr = ab + arow[mi] + ((32 * s + ahi) ^ akey[mi]);
                ldsm4(a[mi][0], a[mi][1], a[mi][2], a[mi][3], addr);
            }
#pragma unroll
            for (int nj2 = 0; nj2 < 4; nj2++) {
                const int row = brow0 + 16 * nj2;
                const unsigned addr = bb + 128u * row + ((32 * s + bsel) ^ ((row & 7) << 4));
                unsigned b0, b1, b2, b3;
                ldsm4(b0, b1, b2, b3, addr);
#pragma unroll
                for (int mi = 0; mi < 4; mi++) {
                    mma_f16(acc[mi][2 * nj2],     a[mi], b0, b1);
                    mma_f16(acc[mi][2 * nj2 + 1], a[mi], b2, b3);
                }
            }
        }
    }
#undef GISSUE

    // ---- epilogue
#pragma unroll
    for (int mi = 0; mi < 4; mi++) {
#pragma unroll
        for (int h = 0; h < 2; h++) {
            const int m  = m0 + wm0 + 16 * mi + gp + 8 * h;
            const int b_ = m >> 11;
            const int s  = m & (S_ - 1);
#pragma unroll
            for (int nj = 0; nj < 8; nj++) {
                const int e  = n0 + wn0 + 8 * nj + 2 * tg;
                const float vx = acc[mi][nj][2 * h]     + bias[e];
                const float vy = acc[mi][nj][2 * h + 1] + bias[e + 1];
                if (mode == 0) {
                    *(float2*)((float*)outp + (size_t)m * D_ + e) = make_float2(vx, vy);
                } else if (mode == 1 || mode == 2) {
                    const int hh = e >> 6, hd = e & 63;
                    const float sc = (mode == 1) ? SC_Q : 1.0f;
                    ((unsigned*)outp)[(((size_t)(b_ * H_ + hh) * S_ + s) << 5) + (hd >> 1)] =
                        pack2(vx * sc, vy * sc);
                } else {
                    // V: natural transposed [b,h,hd][s]
                    const int hh = e >> 6, hd = e & 63;
                    __half* vo = (__half*)outp + (((size_t)(b_ * H_ + hh) * HD_ + hd)) * S_ + s;
                    vo[0]  = __float2half_rn(vx);
                    vo[S_] = __float2half_rn(vy);
                }
            }
        }
    }
}

__global__ __launch_bounds__(128, 2) void qkv_gemm_kernel(
    const float* __restrict__ bq, const float* __restrict__ bk, const float* __restrict__ bv)
{
    const int z = blockIdx.z;
    const unsigned* A = (z == 0) ? g_q16 : (z == 1) ? g_k16 : g_v16;
    const float* b    = (z == 0) ? bq : (z == 1) ? bk : bv;
    void* o           = (z == 0) ? (void*)g_Qh : (z == 1) ? (void*)g_Kh : (void*)g_Vh;
    gemm16_body(A, g_w16[z], b, o, z + 1);
}

__global__ __launch_bounds__(128, 2) void out_gemm_kernel(
    const float* __restrict__ bo, float* __restrict__ out)
{
    gemm16_body(g_Ch, g_w16[3], bo, (void*)out, 0);
}

// ---------------------------------------------------------------------------
// Flash attention fp16. 256 threads (8 warps), Q-tile 128 (16 rows/warp),
// K-tile 64, 3-stage cp.async, ldmatrix K AND V frags.
// Softmax: f16x2 ex2 (P words produced directly) + l via ones-MMA (exact
// sum of the fp16 P actually used in PV; no shuffle, no FADD chain).
// ---------------------------------------------------------------------------
#define FL_KSTG 8192
#define FL_VSTG 8192
#define FL_SMEM (3 * (FL_KSTG + FL_VSTG))   // 49152

__global__ __launch_bounds__(256, 2) void flash_fp16_kernel()
{
    extern __shared__ char fsm[];
    const unsigned smK = (unsigned)__cvta_generic_to_shared(fsm);
    const unsigned smV = smK + 3 * FL_KSTG;

    const int t    = threadIdx.x;
    const int lane = t & 31;
    const int w    = t >> 5;
    const int gp   = lane >> 2;
    const int tg   = lane & 3;
    const int qr0  = w << 4;

    const int bh = blockIdx.y;
    const int q0 = blockIdx.x << 7;

    const unsigned* Qw = g_Qh + (size_t)bh * S_ * 32;
    const unsigned* Kw = g_Kh + (size_t)bh * S_ * 32;
    const unsigned* Vw = g_Vh + (size_t)bh * HD_ * (S_ / 2);

    const int kr0 = t >> 3;
    const int kj  = t & 7;
    const unsigned off0 = 128u * kr0 + ((16u * kj) ^ ((kr0 & 7) << 4));
    const unsigned off1 = 128u * (kr0 + 32) + ((16u * kj) ^ (((kr0 + 32) & 7) << 4));

#define FISSUE(st, it2) do {                                                     \
    const int kn = (it2) << 6;                                                   \
    CP16(smK + (st) * FL_KSTG + off0, Kw + (size_t)(kn + kr0) * 32 + 4 * kj);    \
    CP16(smK + (st) * FL_KSTG + off1, Kw + (size_t)(kn + kr0 + 32) * 32 + 4 * kj); \
    CP16(smV + (st) * FL_VSTG + off0,                                            \
         Vw + (size_t)kr0 * (S_ / 2) + (it2) * 32 + 4 * kj);                     \
    CP16(smV + (st) * FL_VSTG + off1,                                            \
         Vw + (size_t)(kr0 + 32) * (S_ / 2) + (it2) * 32 + 4 * kj);              \
    CP_COMMIT();                                                                 \
} while (0)

    // ---- Q fragments (natural layout, pre-scaled by SC_Q)
    unsigned qa[4][4];
#pragma unroll
    for (int s = 0; s < 4; s++) {
        const unsigned* r0 = Qw + (size_t)(q0 + qr0 + gp) * 32;
        const unsigned* r1 = Qw + (size_t)(q0 + qr0 + 8 + gp) * 32;
        qa[s][0] = r0[8 * s + tg];
        qa[s][1] = r1[8 * s + tg];
        qa[s][2] = r0[8 * s + tg + 4];
        qa[s][3] = r1[8 * s + tg + 4];
    }

    FISSUE(0, 0);
    FISSUE(1, 1);

    const int kbrow0 = ((lane >> 4) << 3) + (lane & 7);
    const int kbsel  = ((lane >> 3) & 1) << 4;

    float m_i[2] = {-1e30f, -1e30f};
    float lacc[4] = {0.0f, 0.0f, 0.0f, 0.0f};   // ones-MMA accumulator
    float o[8][4];
#pragma unroll
    for (int dj = 0; dj < 8; dj++)
#pragma unroll
        for (int q = 0; q < 4; q++) o[dj][q] = 0.0f;

    for (int it = 0; it < 32; it++) {
        if (it == 31) { CP_WAIT0(); } else { CP_WAIT1(); }
        __syncthreads();
        if (it + 2 < 32) FISSUE((it + 2) % 3, it + 2);

        const unsigned kb = smK + (it % 3) * FL_KSTG;
        const unsigned vb = smV + (it % 3) * FL_VSTG;

        // ---- S = Q K^T  (64 keys)
        float s[8][4];
#pragma unroll
        for (int nj = 0; nj < 8; nj++)
#pragma unroll
            for (int q = 0; q < 4; q++) s[nj][q] = 0.0f;

#pragma unroll
        for (int ks = 0; ks < 4; ks++) {
#pragma unroll
            for (int nj2 = 0; nj2 < 4; nj2++) {
                const int row = 16 * nj2 + kbrow0;
                const unsigned addr = kb + 128u * row + ((32 * ks + kbsel) ^ ((row & 7) << 4));
                unsigned b0, b1, b2, b3;
                ldsm4(b0, b1, b2, b3, addr);
                mma_f16(s[2 * nj2],     qa[ks], b0, b1);
                mma_f16(s[2 * nj2 + 1], qa[ks], b2, b3);
            }
        }

        // ---- max + conditional rescale
#pragma unroll
        for (int h = 0; h < 2; h++) {
            float mx = fmaxf(s[0][2 * h], s[0][2 * h + 1]);
#pragma unroll
            for (int nj = 1; nj < 8; nj++)
                mx = fmaxf(mx, fmaxf(s[nj][2 * h], s[nj][2 * h + 1]));
            mx = fmaxf(mx, __shfl_xor_sync(0xffffffffu, mx, 1));
            mx = fmaxf(mx, __shfl_xor_sync(0xffffffffu, mx, 2));
            if (mx > m_i[h]) {
                const float corr = ex2(m_i[h] - mx);
                m_i[h] = mx;
                lacc[2 * h]     *= corr;
                lacc[2 * h + 1] *= corr;
#pragma unroll
                for (int dj = 0; dj < 8; dj++) {
                    o[dj][2 * h]     *= corr;
                    o[dj][2 * h + 1] *= corr;
                }
            }
        }

        // ---- P = exp2(s - m) directly as packed f16x2 fragments
        unsigned pa[4][4];
#pragma unroll
        for (int nj = 0; nj < 8; nj++) {
            const unsigned p0 = ex2h2(pack2(s[nj][0] - m_i[0], s[nj][1] - m_i[0]));
            const unsigned p1 = ex2h2(pack2(s[nj][2] - m_i[1], s[nj][3] - m_i[1]));
            pa[nj >> 1][2 * (nj & 1)]     = p0;
            pa[nj >> 1][2 * (nj & 1) + 1] = p1;
        }

        // ---- l += P @ ones (exact f32 sum of the fp16 P used below)
#pragma unroll
        for (int cp = 0; cp < 4; cp++)
            mma_f16(lacc, pa[cp], ONES2, ONES2);

        // ---- O += P @ V (ldmatrix V frags, natural layout)
#pragma unroll
        for (int cp = 0; cp < 4; cp++) {
#pragma unroll
            for (int dj2 = 0; dj2 < 4; dj2++) {
                const int row = 16 * dj2 + kbrow0;
                const unsigned addr = vb + 128u * row + ((32 * cp + kbsel) ^ ((row & 7) << 4));
                unsigned b0, b1, b2, b3;
                ldsm4(b0, b1, b2, b3, addr);
                mma_f16(o[2 * dj2],     pa[cp], b0, b1);
                mma_f16(o[2 * dj2 + 1], pa[cp], b2, b3);
            }
        }
    }
#undef FISSUE

    // ---- finalize (l = lacc[2h], already full row sum; no shuffle needed)
    const int b_ = bh >> 4;
    const int hh = bh & 15;
#pragma unroll
    for (int h = 0; h < 2; h++) {
        const float inv = 1.0f / lacc[2 * h];
        const int srow = q0 + qr0 + gp + 8 * h;
        unsigned* co = g_Ch + ((size_t)(b_ * S_ + srow) << 9) + (hh << 5);
#pragma unroll
        for (int dj = 0; dj < 8; dj++)
            co[4 * dj + tg] = pack2(o[dj][2 * h] * inv, o[dj][2 * h + 1] * inv);
    }
}

// ---------------------------------------------------------------------------
extern "C" void kernel_launch(void* const* d_in, const int* in_sizes, int n_in,
                              void* d_out, int out_size)
{
    const float* query = (const float*)d_in[0];
    const float* key   = (const float*)d_in[1];
    const float* value = (const float*)d_in[2];
    const float* Wq    = (const float*)d_in[3];
    const float* bq    = (const float*)d_in[4];
    const float* Wk    = (const float*)d_in[5];
    const float* bk    = (const float*)d_in[6];
    const float* Wv    = (const float*)d_in[7];
    const float* bv    = (const float*)d_in[8];
    const float* Wo    = (const float*)d_in[9];
    const float* bo    = (const float*)d_in[10];

    static int smem_set = 0;
    if (!smem_set) {
        cudaFuncSetAttribute(qkv_gemm_kernel,
                             cudaFuncAttributeMaxDynamicSharedMemorySize, GM_SMEM);
        cudaFuncSetAttribute(out_gemm_kernel,
                             cudaFuncAttributeMaxDynamicSharedMemorySize, GM_SMEM);
        cudaFuncSetAttribute(flash_fp16_kernel,
                             cudaFuncAttributeMaxDynamicSharedMemorySize, FL_SMEM);
        smem_set = 1;
    }

    convert_kernel<<<dim3(2048, 1, 7), 256>>>(query, key, value, Wq, Wk, Wv, Wo);

    qkv_gemm_kernel<<<dim3(D_ / 128, M_ / 128, 3), 128, GM_SMEM>>>(bq, bk, bv);

    flash_fp16_kernel<<<dim3(S_ / 128, B_ * H_), 256, FL_SMEM>>>();

    out_gemm_kernel<<<dim3(D_ / 128, M_ / 128), 128, GM_SMEM>>>(bo, (float*)d_out);
}